// round 1
// baseline (speedup 1.0000x reference)
#include <cuda_runtime.h>
#include <math.h>

#define BB 32
#define CC 256
#define CR 64
#define HW 16384   // 128*128

// scratch for per-(b,c) means (allocation-free: __device__ global)
__device__ float g_f0[BB * CC];

// ---------------------------------------------------------------------------
// Kernel 1: f0[b,c] = mean over H*W of x[b,c,:,:]
// one block per (b,c) row: 16384 floats = 4096 float4; 256 threads x 16 float4
// ---------------------------------------------------------------------------
__global__ __launch_bounds__(256) void row_mean_kernel(const float* __restrict__ x) {
    const int row = blockIdx.x;                  // b*C + c
    const float4* __restrict__ p =
        reinterpret_cast<const float4*>(x) + (size_t)row * (HW / 4);
    const int t = threadIdx.x;

    float s = 0.0f;
#pragma unroll
    for (int k = 0; k < 16; k++) {
        float4 v = p[k * 256 + t];
        s += (v.x + v.y) + (v.z + v.w);
    }

    // warp reduce
#pragma unroll
    for (int o = 16; o > 0; o >>= 1)
        s += __shfl_xor_sync(0xffffffffu, s, o);

    __shared__ float part[8];
    if ((t & 31) == 0) part[t >> 5] = s;
    __syncthreads();

    if (t < 8) {
        float v = part[t];
#pragma unroll
        for (int o = 4; o > 0; o >>= 1)
            v += __shfl_xor_sync(0x000000ffu, v, o);
        if (t == 0) g_f0[row] = v * (1.0f / HW);
    }
}

// ---------------------------------------------------------------------------
// Kernel 2: the whole SE MLP + final linear, one block of 256 threads.
//   h = relu(f0 @ W1^T)          (32,64)
//   g = sigmoid(h @ W2^T)        (32,256)
//   p = g * f0                   (computed in-place into f0 buffer)
//   out = p @ W3^T + b3          (32,2)
// smem: f0 32KB + h 8KB = 40KB
// ---------------------------------------------------------------------------
__global__ __launch_bounds__(256) void mlp_kernel(const float* __restrict__ W1,
                                                  const float* __restrict__ W2,
                                                  const float* __restrict__ W3,
                                                  const float* __restrict__ b3,
                                                  float* __restrict__ out) {
    __shared__ float f0[BB][CC];   // later overwritten in-place with p = g*f0
    __shared__ float h[BB][CR];
    const int t = threadIdx.x;

    for (int i = t; i < BB * CC; i += 256)
        ((float*)f0)[i] = g_f0[i];
    __syncthreads();

    // h[b][j] = relu(sum_c f0[b][c] * W1[j][c]) : 2048 dots of length 256
    for (int i = t; i < BB * CR; i += 256) {
        const int b = i / CR, j = i % CR;
        const float* __restrict__ w = W1 + j * CC;
        float acc = 0.0f;
#pragma unroll 8
        for (int c = 0; c < CC; c++) acc = fmaf(f0[b][c], w[c], acc);
        ((float*)h)[i] = fmaxf(acc, 0.0f);
    }
    __syncthreads();

    // p[b][c] = sigmoid(sum_j h[b][j]*W2[c][j]) * f0[b][c]  (in place)
    for (int i = t; i < BB * CC; i += 256) {
        const int b = i / CC, c = i % CC;
        const float* __restrict__ w = W2 + c * CR;
        float acc = 0.0f;
#pragma unroll 8
        for (int j = 0; j < CR; j++) acc = fmaf(h[b][j], w[j], acc);
        const float gsig = 1.0f / (1.0f + expf(-acc));
        f0[b][c] = gsig * f0[b][c];
    }
    __syncthreads();

    // out[b][o] = sum_c p[b][c] * W3[o][c] + b3[o] : 64 dots of length 256
    if (t < BB * 2) {
        const int b = t >> 1, o = t & 1;
        const float* __restrict__ w = W3 + o * CC;
        float acc = b3[o];
#pragma unroll 8
        for (int c = 0; c < CC; c++) acc = fmaf(f0[b][c], w[c], acc);
        out[b * 2 + o] = acc;
    }
}

// ---------------------------------------------------------------------------
extern "C" void kernel_launch(void* const* d_in, const int* in_sizes, int n_in,
                              void* d_out, int out_size) {
    const float* x  = (const float*)d_in[0];  // (32,256,128,128)
    const float* W1 = (const float*)d_in[1];  // (64,256)
    const float* W2 = (const float*)d_in[2];  // (256,64)
    const float* W3 = (const float*)d_in[3];  // (2,256)
    const float* b3 = (const float*)d_in[4];  // (2,)
    float* out = (float*)d_out;               // (32,2)

    row_mean_kernel<<<BB * CC, 256>>>(x);
    mlp_kernel<<<1, 256>>>(W1, W2, W3, b3, out);
}

// round 2
// speedup vs baseline: 7.2304x; 7.2304x over previous
#include <cuda_runtime.h>
#include <math.h>

#define BB 32
#define CC 256
#define CR 64
#define HW 16384   // 128*128

// allocation-free scratch
__device__ float g_f0[BB * CC];   // pooled means
__device__ float g_h [BB * CR];   // relu(f0 @ W1^T)
__device__ float g_p [BB * CC];   // sigmoid(h @ W2^T) * f0

// ---------------------------------------------------------------------------
// Kernel 1: f0[b,c] = mean over H*W of x[b,c,:,:]
// one block per (b,c) row: 4096 float4; 256 threads x 16 float4  (DRAM-bound)
// ---------------------------------------------------------------------------
__global__ __launch_bounds__(256) void row_mean_kernel(const float* __restrict__ x) {
    const int row = blockIdx.x;                  // b*C + c
    const float4* __restrict__ p =
        reinterpret_cast<const float4*>(x) + (size_t)row * (HW / 4);
    const int t = threadIdx.x;

    float s = 0.0f;
#pragma unroll
    for (int k = 0; k < 16; k++) {
        float4 v = p[k * 256 + t];
        s += (v.x + v.y) + (v.z + v.w);
    }

#pragma unroll
    for (int o = 16; o > 0; o >>= 1)
        s += __shfl_xor_sync(0xffffffffu, s, o);

    __shared__ float part[8];
    if ((t & 31) == 0) part[t >> 5] = s;
    __syncthreads();

    if (t < 8) {
        float v = part[t];
#pragma unroll
        for (int o = 4; o > 0; o >>= 1)
            v += __shfl_xor_sync(0x000000ffu, v, o);
        if (t == 0) g_f0[row] = v * (1.0f / HW);
    }
}

// ---------------------------------------------------------------------------
// Kernel 2: h[b,j] = relu( f0[b,:] . W1[j,:] )   -- 2048 outputs, warp each.
// Lanes read consecutive floats of the W1 row -> fully coalesced.
// grid = 256 blocks x 256 threads (8 warps/block)
// ---------------------------------------------------------------------------
__global__ __launch_bounds__(256) void mlp1_kernel(const float* __restrict__ W1) {
    const int warp = blockIdx.x * 8 + (threadIdx.x >> 5);   // 0..2047
    const int lane = threadIdx.x & 31;
    const int b = warp >> 6;          // /64
    const int j = warp & 63;          // %64

    const float* __restrict__ w = W1 + j * CC;
    const float* __restrict__ f = g_f0 + b * CC;

    float acc = 0.0f;
#pragma unroll
    for (int k = 0; k < 8; k++) {
        const int c = k * 32 + lane;
        acc = fmaf(f[c], w[c], acc);
    }
#pragma unroll
    for (int o = 16; o > 0; o >>= 1)
        acc += __shfl_xor_sync(0xffffffffu, acc, o);

    if (lane == 0) g_h[b * CR + j] = fmaxf(acc, 0.0f);
}

// ---------------------------------------------------------------------------
// Kernel 3: p[b,c] = sigmoid( h[b,:] . W2[c,:] ) * f0[b,c] -- 8192 outputs,
// warp each; dot length 64 = 2 coalesced loads per operand.
// grid = 1024 blocks x 256 threads
// ---------------------------------------------------------------------------
__global__ __launch_bounds__(256) void mlp2_kernel(const float* __restrict__ W2) {
    const int warp = blockIdx.x * 8 + (threadIdx.x >> 5);   // 0..8191
    const int lane = threadIdx.x & 31;
    const int b = warp >> 8;          // /256
    const int c = warp & 255;         // %256

    const float* __restrict__ w = W2 + c * CR;
    const float* __restrict__ h = g_h + b * CR;

    float acc = fmaf(h[lane], w[lane], h[lane + 32] * w[lane + 32]);
#pragma unroll
    for (int o = 16; o > 0; o >>= 1)
        acc += __shfl_xor_sync(0xffffffffu, acc, o);

    if (lane == 0) {
        const float gsig = 1.0f / (1.0f + __expf(-acc));
        g_p[b * CC + c] = gsig * g_f0[b * CC + c];
    }
}

// ---------------------------------------------------------------------------
// Kernel 4: out[b,o] = p[b,:] . W3[o,:] + b3[o] -- 64 outputs, warp each.
// grid = 2 blocks x 1024 threads (32 warps each)
// ---------------------------------------------------------------------------
__global__ __launch_bounds__(1024) void mlp3_kernel(const float* __restrict__ W3,
                                                    const float* __restrict__ b3,
                                                    float* __restrict__ out) {
    const int warp = blockIdx.x * 32 + (threadIdx.x >> 5); // 0..63
    const int lane = threadIdx.x & 31;
    const int b = warp >> 1;
    const int o = warp & 1;

    const float* __restrict__ w = W3 + o * CC;
    const float* __restrict__ p = g_p + b * CC;

    float acc = 0.0f;
#pragma unroll
    for (int k = 0; k < 8; k++) {
        const int c = k * 32 + lane;
        acc = fmaf(p[c], w[c], acc);
    }
#pragma unroll
    for (int oo = 16; oo > 0; oo >>= 1)
        acc += __shfl_xor_sync(0xffffffffu, acc, oo);

    if (lane == 0) out[b * 2 + o] = acc + b3[o];
}

// ---------------------------------------------------------------------------
extern "C" void kernel_launch(void* const* d_in, const int* in_sizes, int n_in,
                              void* d_out, int out_size) {
    const float* x  = (const float*)d_in[0];  // (32,256,128,128)
    const float* W1 = (const float*)d_in[1];  // (64,256)
    const float* W2 = (const float*)d_in[2];  // (256,64)
    const float* W3 = (const float*)d_in[3];  // (2,256)
    const float* b3 = (const float*)d_in[4];  // (2,)
    float* out = (float*)d_out;               // (32,2)

    row_mean_kernel<<<BB * CC, 256>>>(x);
    mlp1_kernel<<<256, 256>>>(W1);
    mlp2_kernel<<<1024, 256>>>(W2);
    mlp3_kernel<<<2, 1024>>>(W3, b3, out);
}